// round 2
// baseline (speedup 1.0000x reference)
#include <cuda_runtime.h>

#define Bn 8192
#define Dn 256
#define INn 64
#define ONn 256
#define W1P 260
#define W2P 68

__device__ float g_innerT[(size_t)Dn * Bn];                 // inner acts, [d][b]
__device__ float g_gT[(size_t)INn * Bn];                    // g acts, [i][b]
__device__ float g_lutT[Dn * INn];                          // sorted breakpoints
__device__ __align__(16) float2 g_lutSC[Dn * (INn + 1)];    // segment (S, C)

// ---------------------------------------------------------------------------
// prep: per-d piecewise-linear LUT. inner(x) = S_p * x + C_p for x in seg p.
// one block per d, 64 threads. bitonic sort + signed prefix sums.
// ---------------------------------------------------------------------------
__global__ void kan_prep(const float* __restrict__ w1, const float* __restrict__ b1,
                         const float* __restrict__ w2, const float* __restrict__ b2)
{
    const int d = blockIdx.x;
    const int i = threadIdx.x;
    __shared__ float st[64], sS[64], sC[64], redS[64], redC[64];

    const float w = w1[(d << 6) + i];
    const float b = b1[(d << 6) + i];
    const float v = w2[(d << 6) + i];

    float t, dS, dC, bS, bC;
    if (w == 0.f) {  // degenerate: constant relu(b)*v term
        t = __int_as_float(0x7f800000); dS = 0.f; dC = 0.f;
        bS = 0.f; bC = fmaxf(b, 0.f) * v;
    } else {
        t = -b / w;
        const float pS = w * v, pC = b * v;
        if (w > 0.f) { dS = pS;  dC = pC;  bS = 0.f; bC = 0.f; }   // activates crossing up
        else         { dS = -pS; dC = -pC; bS = pS;  bC = pC; }    // active at -inf, deactivates
    }
    st[i] = t; sS[i] = dS; sC[i] = dC; redS[i] = bS; redC[i] = bC;

    // bitonic sort ascending by st, payload (sS, sC)
    for (int k = 2; k <= 64; k <<= 1) {
        for (int j = k >> 1; j > 0; j >>= 1) {
            __syncthreads();
            const int ixj = i ^ j;
            if (ixj > i) {
                const bool up = ((i & k) == 0);
                const float a = st[i], c = st[ixj];
                if ((a > c) == up) {
                    st[i] = c; st[ixj] = a;
                    float tmp;
                    tmp = sS[i]; sS[i] = sS[ixj]; sS[ixj] = tmp;
                    tmp = sC[i]; sC[i] = sC[ixj]; sC[ixj] = tmp;
                }
            }
        }
    }
    __syncthreads();
    // inclusive prefix sums over signed deltas
    for (int off = 1; off < 64; off <<= 1) {
        float aS = 0.f, aC = 0.f;
        if (i >= off) { aS = sS[i - off]; aC = sC[i - off]; }
        __syncthreads();
        sS[i] += aS; sC[i] += aC;
        __syncthreads();
    }
    if (i == 0) {
        float S0 = 0.f, C0 = 0.f;
        for (int k = 0; k < 64; ++k) { S0 += redS[k]; C0 += redC[k]; }
        C0 += b2[d];
        redS[0] = S0; redC[0] = C0;
        g_lutSC[d * 65] = make_float2(S0, C0);
    }
    __syncthreads();
    const float S0 = redS[0], C0 = redC[0];
    g_lutT[(d << 6) + i] = st[i];
    g_lutSC[d * 65 + i + 1] = make_float2(S0 + sS[i], C0 + sC[i]);
}

// ---------------------------------------------------------------------------
// eval: innerT[d][b] = S_p * x[b][d] + C_p, p = #(t_k <= x) via branchless search
// grid (B/128, D/64), 256 threads, occ 2
// ---------------------------------------------------------------------------
__global__ __launch_bounds__(256, 2) void kan_eval(const float* __restrict__ x)
{
    extern __shared__ float sm[];
    float*  sT  = sm;                       // [64 d][64]
    float2* sSC = (float2*)(sm + 4096);     // [64 d][65]
    float*  sx  = sm + 4096 + 8320;         // [64 d][129] transposed x tile

    const int b0 = blockIdx.x << 7;
    const int d0 = blockIdx.y << 6;
    const int t  = threadIdx.x;

    {
        const float4* gt = (const float4*)(g_lutT + (d0 << 6));
        const float4* gc = ((const float4*)g_lutSC) + (size_t)(d0 >> 6) * 2080;
        for (int k = t; k < 1024; k += 256) ((float4*)sT)[k] = gt[k];
        for (int k = t; k < 2080; k += 256) ((float4*)sSC)[k] = gc[k];
    }
    for (int k = t; k < 2048; k += 256) {
        const int b = k >> 4, c = (k & 15) << 2;
        float4 v = *(const float4*)(x + (size_t)(b0 + b) * Dn + d0 + c);
        sx[(c + 0) * 129 + b] = v.x;
        sx[(c + 1) * 129 + b] = v.y;
        sx[(c + 2) * 129 + b] = v.z;
        sx[(c + 3) * 129 + b] = v.w;
    }
    __syncthreads();

    const int warp = t >> 5, lane = t & 31;
    #pragma unroll 1
    for (int j = 0; j < 8; ++j) {
        const int dl = (warp << 3) + j;
        const float*  tt = sT + (dl << 6);
        const float2* sc = sSC + dl * 65;
        float* op = g_innerT + (size_t)(d0 + dl) * Bn + b0;
        #pragma unroll
        for (int c = 0; c < 4; ++c) {
            const float xv = sx[dl * 129 + lane + (c << 5)];
            int p = 0;
            p += (tt[31]     <= xv) ? 32 : 0;
            p += (tt[p + 15] <= xv) ? 16 : 0;
            p += (tt[p + 7]  <= xv) ? 8  : 0;
            p += (tt[p + 3]  <= xv) ? 4  : 0;
            p += (tt[p + 1]  <= xv) ? 2  : 0;
            p += (tt[p]      <= xv) ? 1  : 0;   // p <= 63 here
            p += (tt[p]      <= xv) ? 1  : 0;   // p can reach 64
            const float2 scv = sc[p];
            op[lane + (c << 5)] = fmaf(scv.x, xv, scv.y);
        }
    }
}

// ---------------------------------------------------------------------------
// kan_g: gT[i][b] = relu(sum_d innerT[d][b]*wo1[i][d] + bo1[i])
// btile=32 -> grid 256, 256 threads, occ 2. thread tile 2i x 4b.
// ---------------------------------------------------------------------------
__global__ __launch_bounds__(256, 2) void kan_g(const float* __restrict__ wo1,
                                                const float* __restrict__ bo1)
{
    extern __shared__ float sm[];
    float* sW1 = sm;                 // [64 i][W1P] padded (hi banks spread)
    float* sIn = sm + 64 * W1P;      // [256 d][32 b]

    const int b0 = blockIdx.x << 5;
    const int t  = threadIdx.x;

    for (int k = t; k < 4096; k += 256) {
        const int i = k >> 6, d4 = (k & 63) << 2;
        *(float4*)(sW1 + i * W1P + d4) = *(const float4*)(wo1 + (i << 8) + d4);
    }
    for (int k = t; k < 2048; k += 256) {
        const int d = k >> 3, b4 = (k & 7) << 2;
        *(float4*)(sIn + (d << 5) + b4) =
            *(const float4*)(g_innerT + (size_t)d * Bn + b0 + b4);
    }
    __syncthreads();

    const int lo = t & 7, hi = t >> 3;     // b-group, i-pair
    float acc[2][4] = {};
    const float* pin = sIn + (lo << 2);
    const float* pw0 = sW1 + (hi << 1) * W1P;
    const float* pw1 = pw0 + W1P;

    #pragma unroll 4
    for (int d = 0; d < 256; d += 4) {
        const float4 wa = *(const float4*)(pw0 + d);
        const float4 wb = *(const float4*)(pw1 + d);
        const float* w0v = (const float*)&wa;
        const float* w1v = (const float*)&wb;
        #pragma unroll
        for (int dd = 0; dd < 4; ++dd) {
            const float4 xv = *(const float4*)(pin + ((d + dd) << 5));
            acc[0][0] = fmaf(xv.x, w0v[dd], acc[0][0]);
            acc[0][1] = fmaf(xv.y, w0v[dd], acc[0][1]);
            acc[0][2] = fmaf(xv.z, w0v[dd], acc[0][2]);
            acc[0][3] = fmaf(xv.w, w0v[dd], acc[0][3]);
            acc[1][0] = fmaf(xv.x, w1v[dd], acc[1][0]);
            acc[1][1] = fmaf(xv.y, w1v[dd], acc[1][1]);
            acc[1][2] = fmaf(xv.z, w1v[dd], acc[1][2]);
            acc[1][3] = fmaf(xv.w, w1v[dd], acc[1][3]);
        }
    }
    const float ba0 = __ldg(bo1 + (hi << 1));
    const float ba1 = __ldg(bo1 + (hi << 1) + 1);
    float4 r0 = make_float4(fmaxf(acc[0][0] + ba0, 0.f), fmaxf(acc[0][1] + ba0, 0.f),
                            fmaxf(acc[0][2] + ba0, 0.f), fmaxf(acc[0][3] + ba0, 0.f));
    float4 r1 = make_float4(fmaxf(acc[1][0] + ba1, 0.f), fmaxf(acc[1][1] + ba1, 0.f),
                            fmaxf(acc[1][2] + ba1, 0.f), fmaxf(acc[1][3] + ba1, 0.f));
    *(float4*)(g_gT + (size_t)(hi << 1) * Bn + b0 + (lo << 2)) = r0;
    *(float4*)(g_gT + (size_t)((hi << 1) + 1) * Bn + b0 + (lo << 2)) = r1;
}

// ---------------------------------------------------------------------------
// kan_out: out[b][o] = sum_i gT[i][b]*wo2[o][i] + bo2[o]
// btile=32 -> grid 256, 256 threads, occ 2. thread tile 4b x 8o (o strided 32).
// ---------------------------------------------------------------------------
__global__ __launch_bounds__(256, 2) void kan_out(const float* __restrict__ wo2,
                                                  const float* __restrict__ bo2,
                                                  float* __restrict__ out)
{
    extern __shared__ float sm[];
    float* sW2 = sm;               // [256 o][W2P] padded
    float* sG  = sm + 256 * W2P;   // [64 i][32 b]

    const int b0 = blockIdx.x << 5;
    const int t  = threadIdx.x;

    for (int k = t; k < 4096; k += 256) {
        const int o = k >> 4, i4 = (k & 15) << 2;
        *(float4*)(sW2 + o * W2P + i4) = *(const float4*)(wo2 + (o << 6) + i4);
    }
    for (int k = t; k < 512; k += 256) {
        const int i = k >> 3, b4 = (k & 7) << 2;
        *(float4*)(sG + (i << 5) + b4) =
            *(const float4*)(g_gT + (size_t)i * Bn + b0 + b4);
    }
    __syncthreads();

    const int lo = t & 7, hi = t >> 3;     // b-group; o = hi + oo*32
    float acc[4][8] = {};
    #pragma unroll 2
    for (int i = 0; i < 64; i += 4) {
        float4 gv[4];
        #pragma unroll
        for (int ii = 0; ii < 4; ++ii)
            gv[ii] = *(const float4*)(sG + ((i + ii) << 5) + (lo << 2));
        #pragma unroll
        for (int oo = 0; oo < 8; ++oo) {
            const float4 wv = *(const float4*)(sW2 + (hi + (oo << 5)) * W2P + i);
            const float* wvf = (const float*)&wv;
            #pragma unroll
            for (int ii = 0; ii < 4; ++ii) {
                const float* gvf = (const float*)&gv[ii];
                #pragma unroll
                for (int bb = 0; bb < 4; ++bb)
                    acc[bb][oo] = fmaf(gvf[bb], wvf[ii], acc[bb][oo]);
            }
        }
    }
    float bv[8];
    #pragma unroll
    for (int oo = 0; oo < 8; ++oo) bv[oo] = __ldg(bo2 + hi + (oo << 5));
    #pragma unroll
    for (int bb = 0; bb < 4; ++bb) {
        float* po = out + (size_t)(b0 + (lo << 2) + bb) * ONn + hi;
        #pragma unroll
        for (int oo = 0; oo < 8; ++oo)
            po[oo << 5] = acc[bb][oo] + bv[oo];
    }
}

// ---------------------------------------------------------------------------
extern "C" void kernel_launch(void* const* d_in, const int* in_sizes, int n_in,
                              void* d_out, int out_size)
{
    const float* x   = (const float*)d_in[0];
    const float* w1  = (const float*)d_in[1];
    const float* b1  = (const float*)d_in[2];
    const float* w2  = (const float*)d_in[3];
    const float* b2  = (const float*)d_in[4];
    const float* wo1 = (const float*)d_in[5];
    const float* bo1 = (const float*)d_in[6];
    const float* wo2 = (const float*)d_in[7];
    const float* bo2 = (const float*)d_in[8];
    float* out = (float*)d_out;

    const int evalsm = (4096 + 8320 + 8256) * 4;     // 82688
    const int gsm    = (64 * W1P + 256 * 32) * 4;    // 99328
    const int osm    = (256 * W2P + 64 * 32) * 4;    // 77824
    cudaFuncSetAttribute(kan_eval, cudaFuncAttributeMaxDynamicSharedMemorySize, evalsm);
    cudaFuncSetAttribute(kan_g,    cudaFuncAttributeMaxDynamicSharedMemorySize, gsm);
    cudaFuncSetAttribute(kan_out,  cudaFuncAttributeMaxDynamicSharedMemorySize, osm);

    kan_prep<<<Dn, 64>>>(w1, b1, w2, b2);
    kan_eval<<<dim3(Bn / 128, Dn / 64), 256, evalsm>>>(x);
    kan_g<<<Bn / 32, 256, gsm>>>(wo1, bo1);
    kan_out<<<Bn / 32, 256, osm>>>(wo2, bo2, out);
}

// round 4
// speedup vs baseline: 1.0457x; 1.0457x over previous
#include <cuda_runtime.h>

#define Bn 8192
#define Dn 256
#define INn 64
#define ONn 256
#define W1P 260
#define WTP 264

__device__ float g_innerT[(size_t)Dn * Bn];                 // inner acts, [d][b]
__device__ float g_lutT[Dn * INn];                          // sorted breakpoints
__device__ __align__(16) float2 g_lutSC[Dn * (INn + 1)];    // segment (S, C)

typedef unsigned long long u64;

__device__ __forceinline__ u64 ffma2(u64 a, u64 b, u64 c) {
    u64 d;
    asm("fma.rn.f32x2 %0, %1, %2, %3;" : "=l"(d) : "l"(a), "l"(b), "l"(c));
    return d;
}
__device__ __forceinline__ u64 pack2(float v) {
    u64 d;
    asm("mov.b64 %0, {%1, %2};" : "=l"(d) : "f"(v), "f"(v));
    return d;
}
__device__ __forceinline__ float2 unpack2(u64 d) {
    float2 r;
    asm("mov.b64 {%0, %1}, %2;" : "=f"(r.x), "=f"(r.y) : "l"(d));
    return r;
}

// ---------------------------------------------------------------------------
// prep: per-d piecewise-linear LUT. inner(x) = S_p * x + C_p for segment p.
// ---------------------------------------------------------------------------
__global__ void kan_prep(const float* __restrict__ w1, const float* __restrict__ b1,
                         const float* __restrict__ w2, const float* __restrict__ b2)
{
    const int d = blockIdx.x;
    const int i = threadIdx.x;
    __shared__ float st[64], sS[64], sC[64], redS[64], redC[64];

    const float w = w1[(d << 6) + i];
    const float b = b1[(d << 6) + i];
    const float v = w2[(d << 6) + i];

    float t, dS, dC, bS, bC;
    if (w == 0.f) {
        t = __int_as_float(0x7f800000); dS = 0.f; dC = 0.f;
        bS = 0.f; bC = fmaxf(b, 0.f) * v;
    } else {
        t = -b / w;
        const float pS = w * v, pC = b * v;
        if (w > 0.f) { dS = pS;  dC = pC;  bS = 0.f; bC = 0.f; }
        else         { dS = -pS; dC = -pC; bS = pS;  bC = pC; }
    }
    st[i] = t; sS[i] = dS; sC[i] = dC; redS[i] = bS; redC[i] = bC;

    for (int k = 2; k <= 64; k <<= 1) {
        for (int j = k >> 1; j > 0; j >>= 1) {
            __syncthreads();
            const int ixj = i ^ j;
            if (ixj > i) {
                const bool up = ((i & k) == 0);
                const float a = st[i], c = st[ixj];
                if ((a > c) == up) {
                    st[i] = c; st[ixj] = a;
                    float tmp;
                    tmp = sS[i]; sS[i] = sS[ixj]; sS[ixj] = tmp;
                    tmp = sC[i]; sC[i] = sC[ixj]; sC[ixj] = tmp;
                }
            }
        }
    }
    __syncthreads();
    for (int off = 1; off < 64; off <<= 1) {
        float aS = 0.f, aC = 0.f;
        if (i >= off) { aS = sS[i - off]; aC = sC[i - off]; }
        __syncthreads();
        sS[i] += aS; sC[i] += aC;
        __syncthreads();
    }
    if (i == 0) {
        float S0 = 0.f, C0 = 0.f;
        for (int k = 0; k < 64; ++k) { S0 += redS[k]; C0 += redC[k]; }
        C0 += b2[d];
        redS[0] = S0; redC[0] = C0;
        g_lutSC[d * 65] = make_float2(S0, C0);
    }
    __syncthreads();
    const float S0 = redS[0], C0 = redC[0];
    g_lutT[(d << 6) + i] = st[i];
    g_lutSC[d * 65 + i + 1] = make_float2(S0 + sS[i], C0 + sC[i]);
}

// ---------------------------------------------------------------------------
// eval: innerT[d][b] = S_p * x[b][d] + C_p via branchless binary search
// ---------------------------------------------------------------------------
__global__ __launch_bounds__(256, 2) void kan_eval(const float* __restrict__ x)
{
    extern __shared__ float sm[];
    float*  sT  = sm;
    float2* sSC = (float2*)(sm + 4096);
    float*  sx  = sm + 4096 + 8320;

    const int b0 = blockIdx.x << 7;
    const int d0 = blockIdx.y << 6;
    const int t  = threadIdx.x;

    {
        const float4* gt = (const float4*)(g_lutT + (d0 << 6));
        const float4* gc = ((const float4*)g_lutSC) + (size_t)(d0 >> 6) * 2080;
        for (int k = t; k < 1024; k += 256) ((float4*)sT)[k] = gt[k];
        for (int k = t; k < 2080; k += 256) ((float4*)sSC)[k] = gc[k];
    }
    for (int k = t; k < 2048; k += 256) {
        const int b = k >> 4, c = (k & 15) << 2;
        float4 v = *(const float4*)(x + (size_t)(b0 + b) * Dn + d0 + c);
        sx[(c + 0) * 129 + b] = v.x;
        sx[(c + 1) * 129 + b] = v.y;
        sx[(c + 2) * 129 + b] = v.z;
        sx[(c + 3) * 129 + b] = v.w;
    }
    __syncthreads();

    const int warp = t >> 5, lane = t & 31;
    #pragma unroll 1
    for (int j = 0; j < 8; ++j) {
        const int dl = (warp << 3) + j;
        const float*  tt = sT + (dl << 6);
        const float2* sc = sSC + dl * 65;
        float* op = g_innerT + (size_t)(d0 + dl) * Bn + b0;
        #pragma unroll
        for (int c = 0; c < 4; ++c) {
            const float xv = sx[dl * 129 + lane + (c << 5)];
            int p = 0;
            p += (tt[31]     <= xv) ? 32 : 0;
            p += (tt[p + 15] <= xv) ? 16 : 0;
            p += (tt[p + 7]  <= xv) ? 8  : 0;
            p += (tt[p + 3]  <= xv) ? 4  : 0;
            p += (tt[p + 1]  <= xv) ? 2  : 0;
            p += (tt[p]      <= xv) ? 1  : 0;
            p += (tt[p]      <= xv) ? 1  : 0;
            const float2 scv = sc[p];
            op[lane + (c << 5)] = fmaf(scv.x, xv, scv.y);
        }
    }
}

// ---------------------------------------------------------------------------
// fused outer MLP: per CTA btile=32. Phase A: g = relu(inner@wo1^T+bo1) via
// f32x2 pairs along b. Phase B: out = g@wo2^T+bo2 via f32x2 pairs along o
// (wo2 transposed into smem, XOR swizzle s(i) = i & 28). grid 256, occ 2.
// ---------------------------------------------------------------------------
__global__ __launch_bounds__(256, 2) void kan_fused(
    const float* __restrict__ wo1, const float* __restrict__ bo1,
    const float* __restrict__ wo2, const float* __restrict__ bo2,
    float* __restrict__ out)
{
    extern __shared__ float sm[];
    float* sW  = sm;                   // phase A: wo1 [64][W1P]; phase B: wo2T [64][WTP]
    float* sIn = sm + 64 * WTP;        // [256 d][32 b]
    float* sG  = sIn + 8192;           // [64 i][32 b]

    const int b0 = blockIdx.x << 5;
    const int t  = threadIdx.x;
    const int lo = t & 7;              // b-group: b = 4*lo + bb
    const int hi = t >> 3;             // 0..31

    // ---- load wo1 + inner tile
    for (int idx = t; idx < 4096; idx += 256) {
        const int i = idx >> 6, d4 = (idx & 63) << 2;
        *(float4*)(sW + i * W1P + d4) = *(const float4*)(wo1 + (i << 8) + d4);
    }
    for (int idx = t; idx < 2048; idx += 256) {
        const int d = idx >> 3, b4 = (idx & 7) << 2;
        *(float4*)(sIn + (d << 5) + b4) =
            *(const float4*)(g_innerT + (size_t)d * Bn + b0 + b4);
    }
    __syncthreads();

    // ---- Phase A: thread tile 4b(2 pairs) x 2i, K=256
    {
        const int i0 = hi << 1;
        u64 acc00 = 0, acc01 = 0, acc10 = 0, acc11 = 0;
        const float* pin = sIn + (lo << 2);
        const float* pw0 = sW + i0 * W1P;
        const float* pw1 = pw0 + W1P;

        #pragma unroll 2
        for (int k = 0; k < 256; k += 4) {
            const float4 wa = *(const float4*)(pw0 + k);
            const float4 wb = *(const float4*)(pw1 + k);
            const float* waf = (const float*)&wa;
            const float* wbf = (const float*)&wb;
            #pragma unroll
            for (int kk = 0; kk < 4; ++kk) {
                const ulonglong2 xv = *(const ulonglong2*)(pin + ((k + kk) << 5));
                const u64 w0d = pack2(waf[kk]);
                const u64 w1d = pack2(wbf[kk]);
                acc00 = ffma2(xv.x, w0d, acc00);
                acc01 = ffma2(xv.y, w0d, acc01);
                acc10 = ffma2(xv.x, w1d, acc10);
                acc11 = ffma2(xv.y, w1d, acc11);
            }
        }
        const float bi0 = __ldg(bo1 + i0);
        const float bi1 = __ldg(bo1 + i0 + 1);
        const float2 a00 = unpack2(acc00), a01 = unpack2(acc01);
        const float2 a10 = unpack2(acc10), a11 = unpack2(acc11);
        float4 r0 = make_float4(fmaxf(a00.x + bi0, 0.f), fmaxf(a00.y + bi0, 0.f),
                                fmaxf(a01.x + bi0, 0.f), fmaxf(a01.y + bi0, 0.f));
        float4 r1 = make_float4(fmaxf(a10.x + bi1, 0.f), fmaxf(a10.y + bi1, 0.f),
                                fmaxf(a11.x + bi1, 0.f), fmaxf(a11.y + bi1, 0.f));
        *(float4*)(sG + (i0 << 5) + (lo << 2)) = r0;
        *(float4*)(sG + ((i0 + 1) << 5) + (lo << 2)) = r1;
    }
    __syncthreads();

    // ---- load wo2 transposed [i][o ^ s(i)], s(i) = i & 28 (constant per
    //      4-row i-group; writer stores whole float4 i-group with one s)
    for (int idx = t; idx < 4096; idx += 256) {
        const int o = idx >> 4, i4 = (idx & 15) << 2;
        const float4 v = *(const float4*)(wo2 + (o << 6) + i4);
        const int osw = o ^ (i4 & 28);
        sW[(i4 + 0) * WTP + osw] = v.x;
        sW[(i4 + 1) * WTP + osw] = v.y;
        sW[(i4 + 2) * WTP + osw] = v.z;
        sW[(i4 + 3) * WTP + osw] = v.w;
    }
    __syncthreads();

    // ---- Phase B: thread tile 4b x 8o (4 o-pairs), K=64
    {
        const int obase = hi << 3;
        u64 acc[4][4];
        #pragma unroll
        for (int bb = 0; bb < 4; ++bb)
            #pragma unroll
            for (int c = 0; c < 4; ++c) acc[bb][c] = 0;

        #pragma unroll 4
        for (int k = 0; k < 64; ++k) {
            const int sw = k & 28;                 // MUST match writer: s(i) = i & 28
            const int pA = obase ^ sw;
            const float* wrow = sW + k * WTP;
            const ulonglong2 wA = *(const ulonglong2*)(wrow + pA);        // o+0..3
            const ulonglong2 wB = *(const ulonglong2*)(wrow + (pA ^ 4));  // o+4..7
            const float4 g4 = *(const float4*)(sG + (k << 5) + (lo << 2));
            const float* gf = (const float*)&g4;
            #pragma unroll
            for (int bb = 0; bb < 4; ++bb) {
                const u64 gd = pack2(gf[bb]);
                acc[bb][0] = ffma2(gd, wA.x, acc[bb][0]);
                acc[bb][1] = ffma2(gd, wA.y, acc[bb][1]);
                acc[bb][2] = ffma2(gd, wB.x, acc[bb][2]);
                acc[bb][3] = ffma2(gd, wB.y, acc[bb][3]);
            }
        }

        const float4 bva = __ldg((const float4*)(bo2 + obase));
        const float4 bvb = __ldg((const float4*)(bo2 + obase + 4));
        #pragma unroll
        for (int bb = 0; bb < 4; ++bb) {
            const float2 p0 = unpack2(acc[bb][0]);
            const float2 p1 = unpack2(acc[bb][1]);
            const float2 p2 = unpack2(acc[bb][2]);
            const float2 p3 = unpack2(acc[bb][3]);
            float* po = out + (size_t)(b0 + (lo << 2) + bb) * ONn + obase;
            *(float4*)(po)     = make_float4(p0.x + bva.x, p0.y + bva.y,
                                             p1.x + bva.z, p1.y + bva.w);
            *(float4*)(po + 4) = make_float4(p2.x + bvb.x, p2.y + bvb.y,
                                             p3.x + bvb.z, p3.y + bvb.w);
        }
    }
}

// ---------------------------------------------------------------------------
extern "C" void kernel_launch(void* const* d_in, const int* in_sizes, int n_in,
                              void* d_out, int out_size)
{
    const float* x   = (const float*)d_in[0];
    const float* w1  = (const float*)d_in[1];
    const float* b1  = (const float*)d_in[2];
    const float* w2  = (const float*)d_in[3];
    const float* b2  = (const float*)d_in[4];
    const float* wo1 = (const float*)d_in[5];
    const float* bo1 = (const float*)d_in[6];
    const float* wo2 = (const float*)d_in[7];
    const float* bo2 = (const float*)d_in[8];
    float* out = (float*)d_out;

    const int evalsm  = (4096 + 8320 + 8256) * 4;            // 82688
    const int fusedsm = (64 * WTP + 8192 + 2048) * 4;        // 108544
    cudaFuncSetAttribute(kan_eval,  cudaFuncAttributeMaxDynamicSharedMemorySize, evalsm);
    cudaFuncSetAttribute(kan_fused, cudaFuncAttributeMaxDynamicSharedMemorySize, fusedsm);

    kan_prep<<<Dn, 64>>>(w1, b1, w2, b2);
    kan_eval<<<dim3(Bn / 128, Dn / 64), 256, evalsm>>>(x);
    kan_fused<<<Bn / 32, 256, fusedsm>>>(wo1, bo1, wo2, bo2, out);
}

// round 5
// speedup vs baseline: 1.0870x; 1.0395x over previous
#include <cuda_runtime.h>

#define Bn 8192
#define Dn 256
#define INn 64
#define ONn 256

__device__ float g_innerT[(size_t)Dn * Bn];                 // inner acts, [d][b]
__device__ float g_lutT[Dn * INn];                          // sorted breakpoints
__device__ __align__(16) float2 g_lutSC[Dn * (INn + 1)];    // segment (S, C)

typedef unsigned long long u64;

__device__ __forceinline__ u64 ffma2(u64 a, u64 b, u64 c) {
    u64 d;
    asm("fma.rn.f32x2 %0, %1, %2, %3;" : "=l"(d) : "l"(a), "l"(b), "l"(c));
    return d;
}
__device__ __forceinline__ float2 unpack2(u64 d) {
    float2 r;
    asm("mov.b64 {%0, %1}, %2;" : "=f"(r.x), "=f"(r.y) : "l"(d));
    return r;
}

// ---------------------------------------------------------------------------
// prep: warp-per-d PWL LUT build. bitonic sort of 64 (2 elems/lane) via shfl,
// prefix sums via shfl. Zero __syncthreads. 32 blocks x 256 threads.
// ---------------------------------------------------------------------------
__device__ __forceinline__ void cmpx(float& key, float& s, float& c,
                                     int j, bool dirUp, int lane) {
    const float ok = __shfl_xor_sync(~0u, key, j);
    const float os = __shfl_xor_sync(~0u, s, j);
    const float oc = __shfl_xor_sync(~0u, c, j);
    const bool lower = ((lane & j) == 0);
    const bool sw = (lower == dirUp) ? (ok < key) : (ok > key);
    if (sw) { key = ok; s = os; c = oc; }
}

__global__ void kan_prep(const float* __restrict__ w1, const float* __restrict__ b1,
                         const float* __restrict__ w2, const float* __restrict__ b2)
{
    const int t = threadIdx.x;
    const int lane = t & 31;
    const int d = (blockIdx.x << 3) + (t >> 5);

    // element e0 = lane, e1 = lane+32
    float k0, s0, c0, k1, s1, c1;
    float baseS = 0.f, baseC = 0.f;
    #pragma unroll
    for (int h = 0; h < 2; ++h) {
        const int j = (d << 6) + lane + (h << 5);
        const float w = w1[j], b = b1[j], v = w2[j];
        float key, dS, dC;
        if (w == 0.f) {
            key = __int_as_float(0x7f800000); dS = 0.f; dC = 0.f;
            baseC += fmaxf(b, 0.f) * v;
        } else {
            key = -b / w;
            const float pS = w * v, pC = b * v;
            if (w > 0.f) { dS = pS;  dC = pC; }
            else         { dS = -pS; dC = -pC; baseS += pS; baseC += pC; }
        }
        if (h == 0) { k0 = key; s0 = dS; c0 = dC; }
        else        { k1 = key; s1 = dS; c1 = dC; }
    }

    // bitonic sort 64 (ascending). stages k=2..32: both halves via shfl.
    for (int k = 2; k <= 32; k <<= 1) {
        const bool d0 = ((lane & k) == 0);
        const bool d1 = (((lane + 32) & k) == 0);
        for (int j = k >> 1; j >= 1; j >>= 1) {
            cmpx(k0, s0, c0, j, d0, lane);
            cmpx(k1, s1, c1, j, d1, lane);
        }
    }
    // stage k=64: j=32 is the in-lane r0/r1 exchange (ascending), then j=16..1
    if (k1 < k0) {
        float tmp;
        tmp = k0; k0 = k1; k1 = tmp;
        tmp = s0; s0 = s1; s1 = tmp;
        tmp = c0; c0 = c1; c1 = tmp;
    }
    for (int j = 16; j >= 1; j >>= 1) {
        cmpx(k0, s0, c0, j, true, lane);
        cmpx(k1, s1, c1, j, true, lane);
    }

    // inclusive prefix sums over sorted (s, c)
    #pragma unroll
    for (int off = 1; off < 32; off <<= 1) {
        const float vs = __shfl_up_sync(~0u, s0, off);
        const float vc = __shfl_up_sync(~0u, c0, off);
        if (lane >= off) { s0 += vs; c0 += vc; }
    }
    const float t0s = __shfl_sync(~0u, s0, 31);
    const float t0c = __shfl_sync(~0u, c0, 31);
    #pragma unroll
    for (int off = 1; off < 32; off <<= 1) {
        const float vs = __shfl_up_sync(~0u, s1, off);
        const float vc = __shfl_up_sync(~0u, c1, off);
        if (lane >= off) { s1 += vs; c1 += vc; }
    }
    s1 += t0s; c1 += t0c;

    // base sums (active-at -inf terms) reduced across warp
    #pragma unroll
    for (int off = 16; off >= 1; off >>= 1) {
        baseS += __shfl_xor_sync(~0u, baseS, off);
        baseC += __shfl_xor_sync(~0u, baseC, off);
    }
    baseC += __ldg(b2 + d);

    g_lutT[(d << 6) + lane]      = k0;
    g_lutT[(d << 6) + lane + 32] = k1;
    if (lane == 0) g_lutSC[d * 65] = make_float2(baseS, baseC);
    g_lutSC[d * 65 + 1 + lane]  = make_float2(baseS + s0, baseC + c0);
    g_lutSC[d * 65 + 33 + lane] = make_float2(baseS + s1, baseC + c1);
}

// ---------------------------------------------------------------------------
// eval: innerT[d][b] = S_p * x[b][d] + C_p via branchless binary search
// ---------------------------------------------------------------------------
__global__ __launch_bounds__(256, 2) void kan_eval(const float* __restrict__ x)
{
    extern __shared__ float sm[];
    float*  sT  = sm;
    float2* sSC = (float2*)(sm + 4096);
    float*  sx  = sm + 4096 + 8320;

    const int b0 = blockIdx.x << 7;
    const int d0 = blockIdx.y << 6;
    const int t  = threadIdx.x;

    {
        const float4* gt = (const float4*)(g_lutT + (d0 << 6));
        const float4* gc = ((const float4*)g_lutSC) + (size_t)(d0 >> 6) * 2080;
        for (int k = t; k < 1024; k += 256) ((float4*)sT)[k] = gt[k];
        for (int k = t; k < 2080; k += 256) ((float4*)sSC)[k] = gc[k];
    }
    for (int k = t; k < 2048; k += 256) {
        const int b = k >> 4, c = (k & 15) << 2;
        float4 v = *(const float4*)(x + (size_t)(b0 + b) * Dn + d0 + c);
        sx[(c + 0) * 129 + b] = v.x;
        sx[(c + 1) * 129 + b] = v.y;
        sx[(c + 2) * 129 + b] = v.z;
        sx[(c + 3) * 129 + b] = v.w;
    }
    __syncthreads();

    const int warp = t >> 5, lane = t & 31;
    #pragma unroll 1
    for (int j = 0; j < 8; ++j) {
        const int dl = (warp << 3) + j;
        const float*  tt = sT + (dl << 6);
        const float2* sc = sSC + dl * 65;
        float* op = g_innerT + (size_t)(d0 + dl) * Bn + b0;
        #pragma unroll
        for (int c = 0; c < 4; ++c) {
            const float xv = sx[dl * 129 + lane + (c << 5)];
            int p = 0;
            p += (tt[31]     <= xv) ? 32 : 0;
            p += (tt[p + 15] <= xv) ? 16 : 0;
            p += (tt[p + 7]  <= xv) ? 8  : 0;
            p += (tt[p + 3]  <= xv) ? 4  : 0;
            p += (tt[p + 1]  <= xv) ? 2  : 0;
            p += (tt[p]      <= xv) ? 1  : 0;
            p += (tt[p]      <= xv) ? 1  : 0;
            const float2 scv = sc[p];
            op[lane + (c << 5)] = fmaf(scv.x, xv, scv.y);
        }
    }
}

// ---------------------------------------------------------------------------
// fused outer MLP, K-paired FFMA2 (no packs: both operands natural pairs).
// 128 threads, btile=32, grid 256 = one wave @ occ 2.
// smem: sW (wo1 [64][260] then wo2 [256][68]) | sIn [32][256] xor-swz | sG [32][64] xor-swz
// ---------------------------------------------------------------------------
#define SW_F 17408
#define SIN_F 8192

__global__ __launch_bounds__(128, 2) void kan_fused(
    const float* __restrict__ wo1, const float* __restrict__ bo1,
    const float* __restrict__ wo2, const float* __restrict__ bo2,
    float* __restrict__ out)
{
    extern __shared__ float sm[];
    float* sW  = sm;                      // phase A: [64][260]; phase B: [256][68]
    float* sIn = sm + SW_F;               // [32 b][256 k], col k ^ 4*(b>>2)
    float* sG  = sIn + SIN_F;             // [32 b][64 i],  col i ^ 4*(b>>2)

    const int b0 = blockIdx.x << 5;
    const int t  = threadIdx.x;
    const int lo = t & 7;                 // b-quad: b = 4*lo + bb
    const int hi = t >> 3;                // 0..15: i-quad / o-quad

    // ---- load wo1 [64][256] -> sW[i][k], stride 260
    for (int idx = t; idx < 4096; idx += 128) {
        const int i = idx >> 6, k4 = (idx & 63) << 2;
        *(float4*)(sW + i * 260 + k4) = *(const float4*)(wo1 + (i << 8) + k4);
    }
    // ---- load inner tile: innerT[d][b0..b0+31] -> sIn[b][d ^ 4*(b>>2)]
    for (int idx = t; idx < 2048; idx += 128) {
        const int dr = idx >> 3, bq = idx & 7;
        const float4 v = *(const float4*)(g_innerT + (size_t)dr * Bn + b0 + (bq << 2));
        const int col = dr ^ (bq << 2);
        sIn[((bq << 2) + 0) * 256 + col] = v.x;
        sIn[((bq << 2) + 1) * 256 + col] = v.y;
        sIn[((bq << 2) + 2) * 256 + col] = v.z;
        sIn[((bq << 2) + 3) * 256 + col] = v.w;
    }
    __syncthreads();

    // ---- Phase A: g[b][i], thread tile 4b x 4i, K=256 paired
    {
        u64 acc[4][4];
        #pragma unroll
        for (int bb = 0; bb < 4; ++bb)
            #pragma unroll
            for (int ii = 0; ii < 4; ++ii) acc[bb][ii] = 0;

        const float* pin = sIn + ((lo << 2) << 8);   // b base row
        const float* pw  = sW + ((hi << 2)) * 260;
        #pragma unroll 2
        for (int k = 0; k < 256; k += 4) {
            const int kx = k ^ (lo << 2);
            ulonglong2 xv[4], wv[4];
            #pragma unroll
            for (int bb = 0; bb < 4; ++bb)
                xv[bb] = *(const ulonglong2*)(pin + (bb << 8) + kx);
            #pragma unroll
            for (int ii = 0; ii < 4; ++ii)
                wv[ii] = *(const ulonglong2*)(pw + ii * 260 + k);
            #pragma unroll
            for (int bb = 0; bb < 4; ++bb)
                #pragma unroll
                for (int ii = 0; ii < 4; ++ii) {
                    acc[bb][ii] = ffma2(xv[bb].x, wv[ii].x, acc[bb][ii]);
                    acc[bb][ii] = ffma2(xv[bb].y, wv[ii].y, acc[bb][ii]);
                }
        }
        const float4 bi = __ldg((const float4*)(bo1 + (hi << 2)));
        const float* bif = (const float*)&bi;
        const int gcol = (hi << 2) ^ (lo << 2);
        #pragma unroll
        for (int bb = 0; bb < 4; ++bb) {
            float r[4];
            #pragma unroll
            for (int ii = 0; ii < 4; ++ii) {
                const float2 p = unpack2(acc[bb][ii]);
                r[ii] = fmaxf(p.x + p.y + bif[ii], 0.f);
            }
            *(float4*)(sG + (((lo << 2) + bb) << 6) + gcol) = *(float4*)r;
        }
    }
    __syncthreads();

    // ---- load wo2 [256][64] -> sW[o][i], stride 68
    for (int idx = t; idx < 4096; idx += 128) {
        const int o = idx >> 4, i4 = (idx & 15) << 2;
        *(float4*)(sW + o * 68 + i4) = *(const float4*)(wo2 + (o << 6) + i4);
    }
    __syncthreads();

    // ---- Phase B: out[b][o], 4 passes of 4b x 4o, K=64 paired
    const float* pg = sG + ((lo << 2) << 6);
    #pragma unroll 1
    for (int p = 0; p < 4; ++p) {
        const int o0 = (hi << 2) + (p << 6);
        u64 acc[4][4];
        #pragma unroll
        for (int bb = 0; bb < 4; ++bb)
            #pragma unroll
            for (int oo = 0; oo < 4; ++oo) acc[bb][oo] = 0;

        const float* pw = sW + o0 * 68;
        #pragma unroll 4
        for (int i = 0; i < 64; i += 4) {
            const int ix = i ^ (lo << 2);
            ulonglong2 gv[4], wv[4];
            #pragma unroll
            for (int bb = 0; bb < 4; ++bb)
                gv[bb] = *(const ulonglong2*)(pg + (bb << 6) + ix);
            #pragma unroll
            for (int oo = 0; oo < 4; ++oo)
                wv[oo] = *(const ulonglong2*)(pw + oo * 68 + i);
            #pragma unroll
            for (int bb = 0; bb < 4; ++bb)
                #pragma unroll
                for (int oo = 0; oo < 4; ++oo) {
                    acc[bb][oo] = ffma2(gv[bb].x, wv[oo].x, acc[bb][oo]);
                    acc[bb][oo] = ffma2(gv[bb].y, wv[oo].y, acc[bb][oo]);
                }
        }
        const float4 bv = __ldg((const float4*)(bo2 + o0));
        const float* bvf = (const float*)&bv;
        #pragma unroll
        for (int bb = 0; bb < 4; ++bb) {
            float r[4];
            #pragma unroll
            for (int oo = 0; oo < 4; ++oo) {
                const float2 q = unpack2(acc[bb][oo]);
                r[oo] = q.x + q.y + bvf[oo];
            }
            *(float4*)(out + (size_t)(b0 + (lo << 2) + bb) * ONn + o0) = *(float4*)r;
        }
    }
}

// ---------------------------------------------------------------------------
extern "C" void kernel_launch(void* const* d_in, const int* in_sizes, int n_in,
                              void* d_out, int out_size)
{
    const float* x   = (const float*)d_in[0];
    const float* w1  = (const float*)d_in[1];
    const float* b1  = (const float*)d_in[2];
    const float* w2  = (const float*)d_in[3];
    const float* b2  = (const float*)d_in[4];
    const float* wo1 = (const float*)d_in[5];
    const float* bo1 = (const float*)d_in[6];
    const float* wo2 = (const float*)d_in[7];
    const float* bo2 = (const float*)d_in[8];
    float* out = (float*)d_out;

    const int evalsm  = (4096 + 8320 + 8256) * 4;            // 82688
    const int fusedsm = (SW_F + SIN_F + 2048) * 4;           // 110592
    cudaFuncSetAttribute(kan_eval,  cudaFuncAttributeMaxDynamicSharedMemorySize, evalsm);
    cudaFuncSetAttribute(kan_fused, cudaFuncAttributeMaxDynamicSharedMemorySize, fusedsm);

    kan_prep<<<Dn / 8, 256>>>(w1, b1, w2, b2);
    kan_eval<<<dim3(Bn / 128, Dn / 64), 256, evalsm>>>(x);
    kan_fused<<<Bn / 32, 128, fusedsm>>>(wo1, bo1, wo2, bo2, out);
}